// round 7
// baseline (speedup 1.0000x reference)
#include <cuda_runtime.h>
#include <cuda_bf16.h>
#include <math.h>
#include <stdint.h>

// ---------------------------------------------------------------------------
// Problem constants
// ---------------------------------------------------------------------------
#define B_     2
#define C_     256
#define N_     4096          // H*W = 64*64
#define HEADS  8
#define HD     32            // C_/HEADS
#define GROUPS 32
#define CPG    8             // C_/GROUPS
#define HID    64            // C_/4
#define EPSF   1e-5f

// ---------------------------------------------------------------------------
// Scratch (static device globals; no allocation allowed)
// ---------------------------------------------------------------------------
__device__ float g_xn [B_ * C_ * N_];        // GN1 output
__device__ float g_qkv[B_ * 3 * C_ * N_];    // qkv  [b][3C][N]
__device__ float g_qkT[B_ * 2 * C_ * N_];    // q,k transposed: [b*2+p][h][i][d]
__device__ float g_att[B_ * C_ * N_];        // attention output (pre-proj)
__device__ float g_x2 [B_ * C_ * N_];        // identity + out-proj
__device__ float g_y  [B_ * C_ * N_];        // GN2 output
__device__ float g_h  [B_ * HID * N_];       // mlp hidden (post gelu)

// ---------------------------------------------------------------------------
// small helpers
// ---------------------------------------------------------------------------
__device__ __forceinline__ float ex2f(float x) {
    float y; asm("ex2.approx.ftz.f32 %0, %1;" : "=f"(y) : "f"(x)); return y;
}
__device__ __forceinline__ uint32_t pkbf(float lo, float hi) {
    uint32_t r; asm("cvt.rn.bf16x2.f32 %0, %1, %2;" : "=r"(r) : "f"(hi), "f"(lo));
    return r;
}
// m16n8k8 tf32 mma, D += A*B
__device__ __forceinline__ void mma_tf32(float* d, const uint32_t* a,
                                         uint32_t b0, uint32_t b1) {
    asm volatile("mma.sync.aligned.m16n8k8.row.col.f32.tf32.tf32.f32 "
        "{%0,%1,%2,%3}, {%4,%5,%6,%7}, {%8,%9}, {%0,%1,%2,%3};"
        : "+f"(d[0]), "+f"(d[1]), "+f"(d[2]), "+f"(d[3])
        : "r"(a[0]), "r"(a[1]), "r"(a[2]), "r"(a[3]), "r"(b0), "r"(b1));
}
// m16n8k16 bf16 mma, D += A*B
__device__ __forceinline__ void mma_bf16(float* d, uint32_t a0, uint32_t a1,
                                         uint32_t a2, uint32_t a3,
                                         uint32_t b0, uint32_t b1) {
    asm volatile("mma.sync.aligned.m16n8k16.row.col.f32.bf16.bf16.f32 "
        "{%0,%1,%2,%3}, {%4,%5,%6,%7}, {%8,%9}, {%0,%1,%2,%3};"
        : "+f"(d[0]), "+f"(d[1]), "+f"(d[2]), "+f"(d[3])
        : "r"(a0), "r"(a1), "r"(a2), "r"(a3), "r"(b0), "r"(b1));
}

// ---------------------------------------------------------------------------
// GroupNorm
// ---------------------------------------------------------------------------
__global__ void __launch_bounds__(256) groupnorm_k(
    const float* __restrict__ x, const float* __restrict__ gamma,
    const float* __restrict__ beta, float* __restrict__ out)
{
    const int g = blockIdx.x;
    const int b = blockIdx.y;
    const size_t base = ((size_t)b * C_ + (size_t)g * CPG) * N_;
    const float4* x4 = reinterpret_cast<const float4*>(x + base);
    float4* o4 = reinterpret_cast<float4*>(out + base);

    float s = 0.f, ss = 0.f;
    for (int i = threadIdx.x; i < (CPG * N_) / 4; i += 256) {
        float4 v = x4[i];
        s  += v.x + v.y + v.z + v.w;
        ss += v.x * v.x + v.y * v.y + v.z * v.z + v.w * v.w;
    }
    __shared__ float rs[8], rss[8];
    #pragma unroll
    for (int o = 16; o > 0; o >>= 1) {
        s  += __shfl_xor_sync(0xffffffffu, s,  o);
        ss += __shfl_xor_sync(0xffffffffu, ss, o);
    }
    int wid = threadIdx.x >> 5;
    if ((threadIdx.x & 31) == 0) { rs[wid] = s; rss[wid] = ss; }
    __syncthreads();
    __shared__ float s_mean, s_rstd;
    if (threadIdx.x == 0) {
        float ts = 0.f, tss = 0.f;
        #pragma unroll
        for (int i = 0; i < 8; i++) { ts += rs[i]; tss += rss[i]; }
        float inv_n = 1.f / (float)(CPG * N_);
        float mean = ts * inv_n;
        float var  = tss * inv_n - mean * mean;
        s_mean = mean;
        s_rstd = rsqrtf(var + EPSF);
    }
    __syncthreads();
    float mean = s_mean, rstd = s_rstd;

    for (int i = threadIdx.x; i < (CPG * N_) / 4; i += 256) {
        int c = g * CPG + (i >> 10);
        float ga = gamma[c] * rstd;
        float be = beta[c] - mean * ga;
        float4 v = x4[i];
        v.x = v.x * ga + be; v.y = v.y * ga + be;
        v.z = v.z * ga + be; v.w = v.w * ga + be;
        o4[i] = v;
    }
}

// ---------------------------------------------------------------------------
// Tiled SGEMM (fp32)
// ---------------------------------------------------------------------------
template<bool BIAS, bool RES, bool GELU>
__global__ void __launch_bounds__(256) sgemm_k(
    const float* __restrict__ W, const float* __restrict__ X,
    const float* __restrict__ bias, const float* __restrict__ res,
    float* __restrict__ out, int M, int K, int NN)
{
    __shared__ float Ws[16][64];
    __shared__ float Xs[16][64];

    const int bz = blockIdx.z;
    const int m0 = blockIdx.y * 64;
    const int n0 = blockIdx.x * 64;
    const int tid = threadIdx.x;
    const int tn = tid & 15;
    const int tm = tid >> 4;

    const float* Xb = X + (size_t)bz * K * NN;

    float acc[4][4];
    #pragma unroll
    for (int i = 0; i < 4; i++)
        #pragma unroll
        for (int j = 0; j < 4; j++) acc[i][j] = 0.f;

    const int wr  = tid >> 2;
    const int wc4 = tid & 3;
    const int xr  = tid >> 4;
    const int xc4 = tid & 15;

    for (int k0 = 0; k0 < K; k0 += 16) {
        float4 wv = *reinterpret_cast<const float4*>(
            W + (size_t)(m0 + wr) * K + k0 + 4 * wc4);
        Ws[4 * wc4 + 0][wr] = wv.x;
        Ws[4 * wc4 + 1][wr] = wv.y;
        Ws[4 * wc4 + 2][wr] = wv.z;
        Ws[4 * wc4 + 3][wr] = wv.w;
        *reinterpret_cast<float4*>(&Xs[xr][4 * xc4]) =
            *reinterpret_cast<const float4*>(Xb + (size_t)(k0 + xr) * NN + n0 + 4 * xc4);
        __syncthreads();

        #pragma unroll
        for (int kk = 0; kk < 16; kk++) {
            float4 wf = *reinterpret_cast<const float4*>(&Ws[kk][4 * tm]);
            float4 xf = *reinterpret_cast<const float4*>(&Xs[kk][4 * tn]);
            float wa[4] = {wf.x, wf.y, wf.z, wf.w};
            float xa[4] = {xf.x, xf.y, xf.z, xf.w};
            #pragma unroll
            for (int i = 0; i < 4; i++)
                #pragma unroll
                for (int j = 0; j < 4; j++)
                    acc[i][j] = fmaf(wa[i], xa[j], acc[i][j]);
        }
        __syncthreads();
    }

    #pragma unroll
    for (int i = 0; i < 4; i++) {
        int m = m0 + 4 * tm + i;
        size_t row = ((size_t)bz * M + m) * NN + n0 + 4 * tn;
        float bv = BIAS ? bias[m] : 0.f;
        float4 v;
        float tmpv[4];
        #pragma unroll
        for (int j = 0; j < 4; j++) {
            float t = acc[i][j] + bv;
            if (GELU) t = 0.5f * t * (1.f + erff(t * 0.70710678118654752f));
            tmpv[j] = t;
        }
        if (RES) {
            float4 r = *reinterpret_cast<const float4*>(res + row);
            tmpv[0] += r.x; tmpv[1] += r.y; tmpv[2] += r.z; tmpv[3] += r.w;
        }
        v.x = tmpv[0]; v.y = tmpv[1]; v.z = tmpv[2]; v.w = tmpv[3];
        *reinterpret_cast<float4*>(out + row) = v;
    }
}

// ---------------------------------------------------------------------------
// Transpose q,k parts of qkv: [b][p*256 + h*32 + d][i] -> qkT[(b*2+p)][h][i][d]
// ---------------------------------------------------------------------------
__global__ void __launch_bounds__(256) transpose_qk(
    const float* __restrict__ qkv, float* __restrict__ qkT)
{
    __shared__ float tile[32][33];
    const int i0 = blockIdx.x * 32;
    const int h  = blockIdx.y;
    const int z  = blockIdx.z;         // b*2 + p
    const int b  = z >> 1, p = z & 1;
    const float* src = qkv + ((size_t)b * 3 * C_ + (size_t)p * C_ + (size_t)h * HD) * N_ + i0;
    #pragma unroll
    for (int k = 0; k < 4; k++) {
        int c = threadIdx.y + 8 * k;
        tile[c][threadIdx.x] = src[(size_t)c * N_ + threadIdx.x];
    }
    __syncthreads();
    float* dst = qkT + (((size_t)z * HEADS + h) * N_ + i0) * HD;
    #pragma unroll
    for (int k = 0; k < 4; k++) {
        int r = threadIdx.y + 8 * k;
        dst[(size_t)r * HD + threadIdx.x] = tile[threadIdx.x][r];
    }
}

// ---------------------------------------------------------------------------
// Flash attention via mma.sync (tf32 QK^T, bf16 P*V).
// CTA = (b, h, 64-query tile); 4 warps, warp w owns query rows q0+16w..+15.
// Key tiles of 64. K smem rows padded to 36 words; V smem (bf16) rows padded
// to 36 words -> conflict-free fragment LDS (bank = 4*(lane>>2)+(lane&3)).
// Online softmax in log2 domain (Q pre-scaled by temp*log2(e)).
// ---------------------------------------------------------------------------
__global__ void __launch_bounds__(128) flash_mma(
    const float* __restrict__ qkT, const float* __restrict__ qkv,
    const float* __restrict__ temp, float* __restrict__ out)
{
    __shared__ float    Ks[64 * 36];     // K tile [64 keys][32 d], pad 36
    __shared__ uint32_t Vs[32 * 36];     // V tile [32 d][64 keys] bf16x2, pad 36 words

    const int tid  = threadIdx.x;
    const int lane = tid & 31;
    const int w    = tid >> 5;
    const int b    = blockIdx.z;
    const int h    = blockIdx.y;
    const int q0   = blockIdx.x * 64;

    const float* qTb = qkT + ((size_t)(b * 2 + 0) * HEADS + h) * N_ * HD;
    const float* kTb = qkT + ((size_t)(b * 2 + 1) * HEADS + h) * N_ * HD;
    const float* vb  = qkv + ((size_t)b * 3 * C_ + 2 * C_ + (size_t)h * HD) * N_;

    const float ts2 = fminf(fmaxf(temp[h], 1e-4f), 10.0f) * 1.4426950408889634f;

    // ---- stage Q tile [64 x 32] (scaled) into Ks, then lift to A-fragments ----
    {
        const float4* src = reinterpret_cast<const float4*>(qTb + (size_t)q0 * HD);
        #pragma unroll
        for (int k = 0; k < 4; k++) {
            int f = tid + 128 * k;              // 512 float4 total
            float4 v = src[f];
            v.x *= ts2; v.y *= ts2; v.z *= ts2; v.w *= ts2;
            *reinterpret_cast<float4*>(&Ks[(f >> 3) * 36 + (f & 7) * 4]) = v;
        }
    }
    __syncthreads();
    uint32_t qa[4][4];
    {
        const int r = lane >> 2, c = lane & 3;
        #pragma unroll
        for (int kt = 0; kt < 4; kt++) {
            qa[kt][0] = __float_as_uint(Ks[(16 * w + r)     * 36 + c     + 8 * kt]);
            qa[kt][1] = __float_as_uint(Ks[(16 * w + r + 8) * 36 + c     + 8 * kt]);
            qa[kt][2] = __float_as_uint(Ks[(16 * w + r)     * 36 + c + 4 + 8 * kt]);
            qa[kt][3] = __float_as_uint(Ks[(16 * w + r + 8) * 36 + c + 4 + 8 * kt]);
        }
    }

    float oacc[4][4];
    #pragma unroll
    for (int i = 0; i < 4; i++)
        #pragma unroll
        for (int j = 0; j < 4; j++) oacc[i][j] = 0.f;
    float m0 = -INFINITY, m1 = -INFINITY, l0 = 0.f, l1 = 0.f;

    // ---- prefetch tile 0 ----
    float4 kreg[4], vreg[4];
    {
        const float4* ks = reinterpret_cast<const float4*>(kTb);
        #pragma unroll
        for (int k = 0; k < 4; k++) kreg[k] = ks[tid + 128 * k];
        #pragma unroll
        for (int k = 0; k < 4; k++) {
            int idx = tid + 128 * k;
            vreg[k] = *reinterpret_cast<const float4*>(
                vb + (size_t)(idx >> 4) * N_ + (idx & 15) * 4);
        }
    }

    for (int t = 0; t < N_ / 64; t++) {
        __syncthreads();   // previous tile fully consumed (and Q frags lifted)
        // ---- store staged tile ----
        #pragma unroll
        for (int k = 0; k < 4; k++) {
            int idx = tid + 128 * k;
            *reinterpret_cast<float4*>(&Ks[(idx >> 3) * 36 + (idx & 7) * 4]) = kreg[k];
        }
        #pragma unroll
        for (int k = 0; k < 4; k++) {
            int idx = tid + 128 * k;
            int row = idx >> 4, c4 = idx & 15;
            Vs[row * 36 + 2 * c4]     = pkbf(vreg[k].x, vreg[k].y);
            Vs[row * 36 + 2 * c4 + 1] = pkbf(vreg[k].z, vreg[k].w);
        }
        __syncthreads();

        // ---- prefetch next tile ----
        if (t + 1 < N_ / 64) {
            const int j0 = (t + 1) * 64;
            const float4* ks = reinterpret_cast<const float4*>(kTb + (size_t)j0 * HD);
            #pragma unroll
            for (int k = 0; k < 4; k++) kreg[k] = ks[tid + 128 * k];
            #pragma unroll
            for (int k = 0; k < 4; k++) {
                int idx = tid + 128 * k;
                vreg[k] = *reinterpret_cast<const float4*>(
                    vb + (size_t)(idx >> 4) * N_ + j0 + (idx & 15) * 4);
            }
        }

        const int r = lane >> 2, c = lane & 3;

        // ---- S = Q K^T (tf32) : 8 n-tiles x 4 k-tiles ----
        float sacc[8][4];
        #pragma unroll
        for (int nt = 0; nt < 8; nt++)
            #pragma unroll
            for (int j = 0; j < 4; j++) sacc[nt][j] = 0.f;
        #pragma unroll
        for (int kt = 0; kt < 4; kt++) {
            #pragma unroll
            for (int nt = 0; nt < 8; nt++) {
                uint32_t b0 = __float_as_uint(Ks[(r + 8 * nt) * 36 + c     + 8 * kt]);
                uint32_t b1 = __float_as_uint(Ks[(r + 8 * nt) * 36 + c + 4 + 8 * kt]);
                mma_tf32(sacc[nt], qa[kt], b0, b1);
            }
        }

        // ---- online softmax (log2 domain) ----
        float t0 = -INFINITY, t1 = -INFINITY;
        #pragma unroll
        for (int nt = 0; nt < 8; nt++) {
            t0 = fmaxf(t0, fmaxf(sacc[nt][0], sacc[nt][1]));
            t1 = fmaxf(t1, fmaxf(sacc[nt][2], sacc[nt][3]));
        }
        t0 = fmaxf(t0, __shfl_xor_sync(0xffffffffu, t0, 1));
        t0 = fmaxf(t0, __shfl_xor_sync(0xffffffffu, t0, 2));
        t1 = fmaxf(t1, __shfl_xor_sync(0xffffffffu, t1, 1));
        t1 = fmaxf(t1, __shfl_xor_sync(0xffffffffu, t1, 2));
        float mn0 = fmaxf(m0, t0), mn1 = fmaxf(m1, t1);
        float corr0 = ex2f(m0 - mn0), corr1 = ex2f(m1 - mn1);
        m0 = mn0; m1 = mn1;

        float ls0 = 0.f, ls1 = 0.f;
        #pragma unroll
        for (int nt = 0; nt < 8; nt++) {
            sacc[nt][0] = ex2f(sacc[nt][0] - mn0);
            sacc[nt][1] = ex2f(sacc[nt][1] - mn0);
            sacc[nt][2] = ex2f(sacc[nt][2] - mn1);
            sacc[nt][3] = ex2f(sacc[nt][3] - mn1);
            ls0 += sacc[nt][0] + sacc[nt][1];
            ls1 += sacc[nt][2] + sacc[nt][3];
        }
        ls0 += __shfl_xor_sync(0xffffffffu, ls0, 1);
        ls0 += __shfl_xor_sync(0xffffffffu, ls0, 2);
        ls1 += __shfl_xor_sync(0xffffffffu, ls1, 1);
        ls1 += __shfl_xor_sync(0xffffffffu, ls1, 2);
        l0 = l0 * corr0 + ls0;
        l1 = l1 * corr1 + ls1;
        #pragma unroll
        for (int nt2 = 0; nt2 < 4; nt2++) {
            oacc[nt2][0] *= corr0; oacc[nt2][1] *= corr0;
            oacc[nt2][2] *= corr1; oacc[nt2][3] *= corr1;
        }

        // ---- O += P V (bf16) : P frags straight from S accumulators ----
        #pragma unroll
        for (int kt = 0; kt < 4; kt++) {
            uint32_t a0 = pkbf(sacc[2 * kt][0],     sacc[2 * kt][1]);
            uint32_t a1 = pkbf(sacc[2 * kt][2],     sacc[2 * kt][3]);
            uint32_t a2 = pkbf(sacc[2 * kt + 1][0], sacc[2 * kt + 1][1]);
            uint32_t a3 = pkbf(sacc[2 * kt + 1][2], sacc[2 * kt + 1][3]);
            #pragma unroll
            for (int nt2 = 0; nt2 < 4; nt2++) {
                uint32_t b0 = Vs[(r + 8 * nt2) * 36 + c + 8 * kt];
                uint32_t b1 = Vs[(r + 8 * nt2) * 36 + c + 8 * kt + 4];
                mma_bf16(oacc[nt2], a0, a1, a2, a3, b0, b1);
            }
        }
    }

    // ---- write out: att[(b*C + h*32 + d)*N + i] ----
    const float inv0 = 1.f / l0, inv1 = 1.f / l1;
    const int r = lane >> 2, c = lane & 3;
    const int i0 = q0 + 16 * w + r;
    float* ob = out + ((size_t)b * C_ + (size_t)h * HD) * N_;
    #pragma unroll
    for (int nt2 = 0; nt2 < 4; nt2++) {
        int d = 8 * nt2 + 2 * c;
        ob[(size_t)d       * N_ + i0]     = oacc[nt2][0] * inv0;
        ob[(size_t)(d + 1) * N_ + i0]     = oacc[nt2][1] * inv0;
        ob[(size_t)d       * N_ + i0 + 8] = oacc[nt2][2] * inv1;
        ob[(size_t)(d + 1) * N_ + i0 + 8] = oacc[nt2][3] * inv1;
    }
}

// ---------------------------------------------------------------------------
// Launch
// ---------------------------------------------------------------------------
extern "C" void kernel_launch(void* const* d_in, const int* in_sizes, int n_in,
                              void* d_out, int out_size)
{
    const float* x      = (const float*)d_in[0];
    const float* w_qkv  = (const float*)d_in[1];
    const float* w_out  = (const float*)d_in[2];
    const float* b_out  = (const float*)d_in[3];
    const float* temper = (const float*)d_in[4];
    const float* g1     = (const float*)d_in[5];
    const float* beta1  = (const float*)d_in[6];
    const float* g2     = (const float*)d_in[7];
    const float* beta2  = (const float*)d_in[8];
    const float* w_mlp1 = (const float*)d_in[9];
    const float* b_mlp1 = (const float*)d_in[10];
    const float* w_mlp2 = (const float*)d_in[11];
    const float* b_mlp2 = (const float*)d_in[12];
    float* outp = (float*)d_out;

    float *xn, *qkv, *qkT, *att, *x2, *y, *hb;
    cudaGetSymbolAddress((void**)&xn,  g_xn);
    cudaGetSymbolAddress((void**)&qkv, g_qkv);
    cudaGetSymbolAddress((void**)&qkT, g_qkT);
    cudaGetSymbolAddress((void**)&att, g_att);
    cudaGetSymbolAddress((void**)&x2,  g_x2);
    cudaGetSymbolAddress((void**)&y,   g_y);
    cudaGetSymbolAddress((void**)&hb,  g_h);

    // 1) GroupNorm 1
    groupnorm_k<<<dim3(GROUPS, B_), 256>>>(x, g1, beta1, xn);
    // 2) QKV 1x1 conv
    sgemm_k<false, false, false><<<dim3(N_ / 64, (3 * C_) / 64, B_), 256>>>(
        w_qkv, xn, nullptr, nullptr, qkv, 3 * C_, C_, N_);
    // 2b) transpose q,k to token-major
    transpose_qk<<<dim3(N_ / 32, HEADS, 2 * B_), dim3(32, 8)>>>(qkv, qkT);
    // 3) Attention (mma.sync: tf32 QK^T, bf16 PV)
    flash_mma<<<dim3(N_ / 64, HEADS, B_), 128>>>(qkT, qkv, temper, att);
    // 4) Out-proj + bias + residual(x)
    sgemm_k<true, true, false><<<dim3(N_ / 64, C_ / 64, B_), 256>>>(
        w_out, att, b_out, x, x2, C_, C_, N_);
    // 5) GroupNorm 2
    groupnorm_k<<<dim3(GROUPS, B_), 256>>>(x2, g2, beta2, y);
    // 6) MLP1 + bias + gelu
    sgemm_k<true, false, true><<<dim3(N_ / 64, HID / 64, B_), 256>>>(
        w_mlp1, y, b_mlp1, nullptr, hb, HID, C_, N_);
    // 7) MLP2 + bias + residual(x2) -> output
    sgemm_k<true, true, false><<<dim3(N_ / 64, C_ / 64, B_), 256>>>(
        w_mlp2, hb, b_mlp2, x2, outp, C_, HID, N_);
}

// round 8
// speedup vs baseline: 1.0024x; 1.0024x over previous
#include <cuda_runtime.h>
#include <cuda_bf16.h>
#include <math.h>
#include <stdint.h>

// ---------------------------------------------------------------------------
// Problem constants
// ---------------------------------------------------------------------------
#define B_     2
#define C_     256
#define N_     4096          // H*W = 64*64
#define HEADS  8
#define HD     32            // C_/HEADS
#define GROUPS 32
#define CPG    8             // C_/GROUPS
#define HID    64            // C_/4
#define EPSF   1e-5f

// ---------------------------------------------------------------------------
// Scratch (static device globals; no allocation allowed)
// ---------------------------------------------------------------------------
__device__ float g_xn [B_ * C_ * N_];        // GN1 output
__device__ float g_qkv[B_ * 3 * C_ * N_];    // qkv  [b][3C][N]
__device__ float g_qkT[B_ * 2 * C_ * N_];    // q,k transposed: [b*2+p][h][i][d]
__device__ float g_att[B_ * C_ * N_];        // attention output (pre-proj)
__device__ float g_x2 [B_ * C_ * N_];        // identity + out-proj
__device__ float g_y  [B_ * C_ * N_];        // GN2 output
__device__ float g_h  [B_ * HID * N_];       // mlp hidden (post gelu)

// ---------------------------------------------------------------------------
// small helpers
// ---------------------------------------------------------------------------
__device__ __forceinline__ float ex2f(float x) {
    float y; asm("ex2.approx.ftz.f32 %0, %1;" : "=f"(y) : "f"(x)); return y;
}
__device__ __forceinline__ uint32_t pkbf(float lo, float hi) {
    uint32_t r; asm("cvt.rn.bf16x2.f32 %0, %1, %2;" : "=r"(r) : "f"(hi), "f"(lo));
    return r;
}
// m16n8k8 tf32 mma, D += A*B
__device__ __forceinline__ void mma_tf32(float* d, const uint32_t* a,
                                         uint32_t b0, uint32_t b1) {
    asm volatile("mma.sync.aligned.m16n8k8.row.col.f32.tf32.tf32.f32 "
        "{%0,%1,%2,%3}, {%4,%5,%6,%7}, {%8,%9}, {%0,%1,%2,%3};"
        : "+f"(d[0]), "+f"(d[1]), "+f"(d[2]), "+f"(d[3])
        : "r"(a[0]), "r"(a[1]), "r"(a[2]), "r"(a[3]), "r"(b0), "r"(b1));
}
// m16n8k16 bf16 mma, D += A*B
__device__ __forceinline__ void mma_bf16(float* d, uint32_t a0, uint32_t a1,
                                         uint32_t a2, uint32_t a3,
                                         uint32_t b0, uint32_t b1) {
    asm volatile("mma.sync.aligned.m16n8k16.row.col.f32.bf16.bf16.f32 "
        "{%0,%1,%2,%3}, {%4,%5,%6,%7}, {%8,%9}, {%0,%1,%2,%3};"
        : "+f"(d[0]), "+f"(d[1]), "+f"(d[2]), "+f"(d[3])
        : "r"(a0), "r"(a1), "r"(a2), "r"(a3), "r"(b0), "r"(b1));
}

// ---------------------------------------------------------------------------
// GroupNorm
// ---------------------------------------------------------------------------
__global__ void __launch_bounds__(256) groupnorm_k(
    const float* __restrict__ x, const float* __restrict__ gamma,
    const float* __restrict__ beta, float* __restrict__ out)
{
    const int g = blockIdx.x;
    const int b = blockIdx.y;
    const size_t base = ((size_t)b * C_ + (size_t)g * CPG) * N_;
    const float4* x4 = reinterpret_cast<const float4*>(x + base);
    float4* o4 = reinterpret_cast<float4*>(out + base);

    float s = 0.f, ss = 0.f;
    for (int i = threadIdx.x; i < (CPG * N_) / 4; i += 256) {
        float4 v = x4[i];
        s  += v.x + v.y + v.z + v.w;
        ss += v.x * v.x + v.y * v.y + v.z * v.z + v.w * v.w;
    }
    __shared__ float rs[8], rss[8];
    #pragma unroll
    for (int o = 16; o > 0; o >>= 1) {
        s  += __shfl_xor_sync(0xffffffffu, s,  o);
        ss += __shfl_xor_sync(0xffffffffu, ss, o);
    }
    int wid = threadIdx.x >> 5;
    if ((threadIdx.x & 31) == 0) { rs[wid] = s; rss[wid] = ss; }
    __syncthreads();
    __shared__ float s_mean, s_rstd;
    if (threadIdx.x == 0) {
        float ts = 0.f, tss = 0.f;
        #pragma unroll
        for (int i = 0; i < 8; i++) { ts += rs[i]; tss += rss[i]; }
        float inv_n = 1.f / (float)(CPG * N_);
        float mean = ts * inv_n;
        float var  = tss * inv_n - mean * mean;
        s_mean = mean;
        s_rstd = rsqrtf(var + EPSF);
    }
    __syncthreads();
    float mean = s_mean, rstd = s_rstd;

    for (int i = threadIdx.x; i < (CPG * N_) / 4; i += 256) {
        int c = g * CPG + (i >> 10);
        float ga = gamma[c] * rstd;
        float be = beta[c] - mean * ga;
        float4 v = x4[i];
        v.x = v.x * ga + be; v.y = v.y * ga + be;
        v.z = v.z * ga + be; v.w = v.w * ga + be;
        o4[i] = v;
    }
}

// ---------------------------------------------------------------------------
// Tiled SGEMM (fp32)
// ---------------------------------------------------------------------------
template<bool BIAS, bool RES, bool GELU>
__global__ void __launch_bounds__(256) sgemm_k(
    const float* __restrict__ W, const float* __restrict__ X,
    const float* __restrict__ bias, const float* __restrict__ res,
    float* __restrict__ out, int M, int K, int NN)
{
    __shared__ float Ws[16][64];
    __shared__ float Xs[16][64];

    const int bz = blockIdx.z;
    const int m0 = blockIdx.y * 64;
    const int n0 = blockIdx.x * 64;
    const int tid = threadIdx.x;
    const int tn = tid & 15;
    const int tm = tid >> 4;

    const float* Xb = X + (size_t)bz * K * NN;

    float acc[4][4];
    #pragma unroll
    for (int i = 0; i < 4; i++)
        #pragma unroll
        for (int j = 0; j < 4; j++) acc[i][j] = 0.f;

    const int wr  = tid >> 2;
    const int wc4 = tid & 3;
    const int xr  = tid >> 4;
    const int xc4 = tid & 15;

    for (int k0 = 0; k0 < K; k0 += 16) {
        float4 wv = *reinterpret_cast<const float4*>(
            W + (size_t)(m0 + wr) * K + k0 + 4 * wc4);
        Ws[4 * wc4 + 0][wr] = wv.x;
        Ws[4 * wc4 + 1][wr] = wv.y;
        Ws[4 * wc4 + 2][wr] = wv.z;
        Ws[4 * wc4 + 3][wr] = wv.w;
        *reinterpret_cast<float4*>(&Xs[xr][4 * xc4]) =
            *reinterpret_cast<const float4*>(Xb + (size_t)(k0 + xr) * NN + n0 + 4 * xc4);
        __syncthreads();

        #pragma unroll
        for (int kk = 0; kk < 16; kk++) {
            float4 wf = *reinterpret_cast<const float4*>(&Ws[kk][4 * tm]);
            float4 xf = *reinterpret_cast<const float4*>(&Xs[kk][4 * tn]);
            float wa[4] = {wf.x, wf.y, wf.z, wf.w};
            float xa[4] = {xf.x, xf.y, xf.z, xf.w};
            #pragma unroll
            for (int i = 0; i < 4; i++)
                #pragma unroll
                for (int j = 0; j < 4; j++)
                    acc[i][j] = fmaf(wa[i], xa[j], acc[i][j]);
        }
        __syncthreads();
    }

    #pragma unroll
    for (int i = 0; i < 4; i++) {
        int m = m0 + 4 * tm + i;
        size_t row = ((size_t)bz * M + m) * NN + n0 + 4 * tn;
        float bv = BIAS ? bias[m] : 0.f;
        float4 v;
        float tmpv[4];
        #pragma unroll
        for (int j = 0; j < 4; j++) {
            float t = acc[i][j] + bv;
            if (GELU) t = 0.5f * t * (1.f + erff(t * 0.70710678118654752f));
            tmpv[j] = t;
        }
        if (RES) {
            float4 r = *reinterpret_cast<const float4*>(res + row);
            tmpv[0] += r.x; tmpv[1] += r.y; tmpv[2] += r.z; tmpv[3] += r.w;
        }
        v.x = tmpv[0]; v.y = tmpv[1]; v.z = tmpv[2]; v.w = tmpv[3];
        *reinterpret_cast<float4*>(out + row) = v;
    }
}

// ---------------------------------------------------------------------------
// Transpose q,k parts of qkv: [b][p*256 + h*32 + d][i] -> qkT[(b*2+p)][h][i][d]
// ---------------------------------------------------------------------------
__global__ void __launch_bounds__(256) transpose_qk(
    const float* __restrict__ qkv, float* __restrict__ qkT)
{
    __shared__ float tile[32][33];
    const int i0 = blockIdx.x * 32;
    const int h  = blockIdx.y;
    const int z  = blockIdx.z;         // b*2 + p
    const int b  = z >> 1, p = z & 1;
    const float* src = qkv + ((size_t)b * 3 * C_ + (size_t)p * C_ + (size_t)h * HD) * N_ + i0;
    #pragma unroll
    for (int k = 0; k < 4; k++) {
        int c = threadIdx.y + 8 * k;
        tile[c][threadIdx.x] = src[(size_t)c * N_ + threadIdx.x];
    }
    __syncthreads();
    float* dst = qkT + (((size_t)z * HEADS + h) * N_ + i0) * HD;
    #pragma unroll
    for (int k = 0; k < 4; k++) {
        int r = threadIdx.y + 8 * k;
        dst[(size_t)r * HD + threadIdx.x] = tile[threadIdx.x][r];
    }
}

// ---------------------------------------------------------------------------
// Flash attention via mma.sync (tf32 QK^T, bf16 P*V).
// CTA = (b, h, 64-query tile); 4 warps, warp w owns query rows q0+16w..+15.
// Key tiles of 64. K smem rows padded to 36 words; V smem (bf16) rows padded
// to 36 words -> conflict-free fragment LDS (bank = 4*(lane>>2)+(lane&3)).
// Online softmax in log2 domain (Q pre-scaled by temp*log2(e)).
// ---------------------------------------------------------------------------
__global__ void __launch_bounds__(128) flash_mma(
    const float* __restrict__ qkT, const float* __restrict__ qkv,
    const float* __restrict__ temp, float* __restrict__ out)
{
    __shared__ float    Ks[64 * 36];     // K tile [64 keys][32 d], pad 36
    __shared__ uint32_t Vs[32 * 36];     // V tile [32 d][64 keys] bf16x2, pad 36 words

    const int tid  = threadIdx.x;
    const int lane = tid & 31;
    const int w    = tid >> 5;
    const int b    = blockIdx.z;
    const int h    = blockIdx.y;
    const int q0   = blockIdx.x * 64;

    const float* qTb = qkT + ((size_t)(b * 2 + 0) * HEADS + h) * N_ * HD;
    const float* kTb = qkT + ((size_t)(b * 2 + 1) * HEADS + h) * N_ * HD;
    const float* vb  = qkv + ((size_t)b * 3 * C_ + 2 * C_ + (size_t)h * HD) * N_;

    const float ts2 = fminf(fmaxf(temp[h], 1e-4f), 10.0f) * 1.4426950408889634f;

    // ---- stage Q tile [64 x 32] (scaled) into Ks, then lift to A-fragments ----
    {
        const float4* src = reinterpret_cast<const float4*>(qTb + (size_t)q0 * HD);
        #pragma unroll
        for (int k = 0; k < 4; k++) {
            int f = tid + 128 * k;              // 512 float4 total
            float4 v = src[f];
            v.x *= ts2; v.y *= ts2; v.z *= ts2; v.w *= ts2;
            *reinterpret_cast<float4*>(&Ks[(f >> 3) * 36 + (f & 7) * 4]) = v;
        }
    }
    __syncthreads();
    uint32_t qa[4][4];
    {
        const int r = lane >> 2, c = lane & 3;
        #pragma unroll
        for (int kt = 0; kt < 4; kt++) {
            qa[kt][0] = __float_as_uint(Ks[(16 * w + r)     * 36 + c     + 8 * kt]);
            qa[kt][1] = __float_as_uint(Ks[(16 * w + r + 8) * 36 + c     + 8 * kt]);
            qa[kt][2] = __float_as_uint(Ks[(16 * w + r)     * 36 + c + 4 + 8 * kt]);
            qa[kt][3] = __float_as_uint(Ks[(16 * w + r + 8) * 36 + c + 4 + 8 * kt]);
        }
    }

    float oacc[4][4];
    #pragma unroll
    for (int i = 0; i < 4; i++)
        #pragma unroll
        for (int j = 0; j < 4; j++) oacc[i][j] = 0.f;
    float m0 = -INFINITY, m1 = -INFINITY, l0 = 0.f, l1 = 0.f;

    // ---- prefetch tile 0 ----
    float4 kreg[4], vreg[4];
    {
        const float4* ks = reinterpret_cast<const float4*>(kTb);
        #pragma unroll
        for (int k = 0; k < 4; k++) kreg[k] = ks[tid + 128 * k];
        #pragma unroll
        for (int k = 0; k < 4; k++) {
            int idx = tid + 128 * k;
            vreg[k] = *reinterpret_cast<const float4*>(
                vb + (size_t)(idx >> 4) * N_ + (idx & 15) * 4);
        }
    }

    for (int t = 0; t < N_ / 64; t++) {
        __syncthreads();   // previous tile fully consumed (and Q frags lifted)
        // ---- store staged tile ----
        #pragma unroll
        for (int k = 0; k < 4; k++) {
            int idx = tid + 128 * k;
            *reinterpret_cast<float4*>(&Ks[(idx >> 3) * 36 + (idx & 7) * 4]) = kreg[k];
        }
        #pragma unroll
        for (int k = 0; k < 4; k++) {
            int idx = tid + 128 * k;
            int row = idx >> 4, c4 = idx & 15;
            Vs[row * 36 + 2 * c4]     = pkbf(vreg[k].x, vreg[k].y);
            Vs[row * 36 + 2 * c4 + 1] = pkbf(vreg[k].z, vreg[k].w);
        }
        __syncthreads();

        // ---- prefetch next tile ----
        if (t + 1 < N_ / 64) {
            const int j0 = (t + 1) * 64;
            const float4* ks = reinterpret_cast<const float4*>(kTb + (size_t)j0 * HD);
            #pragma unroll
            for (int k = 0; k < 4; k++) kreg[k] = ks[tid + 128 * k];
            #pragma unroll
            for (int k = 0; k < 4; k++) {
                int idx = tid + 128 * k;
                vreg[k] = *reinterpret_cast<const float4*>(
                    vb + (size_t)(idx >> 4) * N_ + j0 + (idx & 15) * 4);
            }
        }

        const int r = lane >> 2, c = lane & 3;

        // ---- S = Q K^T (tf32) : 8 n-tiles x 4 k-tiles ----
        float sacc[8][4];
        #pragma unroll
        for (int nt = 0; nt < 8; nt++)
            #pragma unroll
            for (int j = 0; j < 4; j++) sacc[nt][j] = 0.f;
        #pragma unroll
        for (int kt = 0; kt < 4; kt++) {
            #pragma unroll
            for (int nt = 0; nt < 8; nt++) {
                uint32_t b0 = __float_as_uint(Ks[(r + 8 * nt) * 36 + c     + 8 * kt]);
                uint32_t b1 = __float_as_uint(Ks[(r + 8 * nt) * 36 + c + 4 + 8 * kt]);
                mma_tf32(sacc[nt], qa[kt], b0, b1);
            }
        }

        // ---- online softmax (log2 domain) ----
        float t0 = -INFINITY, t1 = -INFINITY;
        #pragma unroll
        for (int nt = 0; nt < 8; nt++) {
            t0 = fmaxf(t0, fmaxf(sacc[nt][0], sacc[nt][1]));
            t1 = fmaxf(t1, fmaxf(sacc[nt][2], sacc[nt][3]));
        }
        t0 = fmaxf(t0, __shfl_xor_sync(0xffffffffu, t0, 1));
        t0 = fmaxf(t0, __shfl_xor_sync(0xffffffffu, t0, 2));
        t1 = fmaxf(t1, __shfl_xor_sync(0xffffffffu, t1, 1));
        t1 = fmaxf(t1, __shfl_xor_sync(0xffffffffu, t1, 2));
        float mn0 = fmaxf(m0, t0), mn1 = fmaxf(m1, t1);
        float corr0 = ex2f(m0 - mn0), corr1 = ex2f(m1 - mn1);
        m0 = mn0; m1 = mn1;

        float ls0 = 0.f, ls1 = 0.f;
        #pragma unroll
        for (int nt = 0; nt < 8; nt++) {
            sacc[nt][0] = ex2f(sacc[nt][0] - mn0);
            sacc[nt][1] = ex2f(sacc[nt][1] - mn0);
            sacc[nt][2] = ex2f(sacc[nt][2] - mn1);
            sacc[nt][3] = ex2f(sacc[nt][3] - mn1);
            ls0 += sacc[nt][0] + sacc[nt][1];
            ls1 += sacc[nt][2] + sacc[nt][3];
        }
        ls0 += __shfl_xor_sync(0xffffffffu, ls0, 1);
        ls0 += __shfl_xor_sync(0xffffffffu, ls0, 2);
        ls1 += __shfl_xor_sync(0xffffffffu, ls1, 1);
        ls1 += __shfl_xor_sync(0xffffffffu, ls1, 2);
        l0 = l0 * corr0 + ls0;
        l1 = l1 * corr1 + ls1;
        #pragma unroll
        for (int nt2 = 0; nt2 < 4; nt2++) {
            oacc[nt2][0] *= corr0; oacc[nt2][1] *= corr0;
            oacc[nt2][2] *= corr1; oacc[nt2][3] *= corr1;
        }

        // ---- O += P V (bf16) : P frags straight from S accumulators ----
        #pragma unroll
        for (int kt = 0; kt < 4; kt++) {
            uint32_t a0 = pkbf(sacc[2 * kt][0],     sacc[2 * kt][1]);
            uint32_t a1 = pkbf(sacc[2 * kt][2],     sacc[2 * kt][3]);
            uint32_t a2 = pkbf(sacc[2 * kt + 1][0], sacc[2 * kt + 1][1]);
            uint32_t a3 = pkbf(sacc[2 * kt + 1][2], sacc[2 * kt + 1][3]);
            #pragma unroll
            for (int nt2 = 0; nt2 < 4; nt2++) {
                uint32_t b0 = Vs[(r + 8 * nt2) * 36 + c + 8 * kt];
                uint32_t b1 = Vs[(r + 8 * nt2) * 36 + c + 8 * kt + 4];
                mma_bf16(oacc[nt2], a0, a1, a2, a3, b0, b1);
            }
        }
    }

    // ---- write out: att[(b*C + h*32 + d)*N + i] ----
    const float inv0 = 1.f / l0, inv1 = 1.f / l1;
    const int r = lane >> 2, c = lane & 3;
    const int i0 = q0 + 16 * w + r;
    float* ob = out + ((size_t)b * C_ + (size_t)h * HD) * N_;
    #pragma unroll
    for (int nt2 = 0; nt2 < 4; nt2++) {
        int d = 8 * nt2 + 2 * c;
        ob[(size_t)d       * N_ + i0]     = oacc[nt2][0] * inv0;
        ob[(size_t)(d + 1) * N_ + i0]     = oacc[nt2][1] * inv0;
        ob[(size_t)d       * N_ + i0 + 8] = oacc[nt2][2] * inv1;
        ob[(size_t)(d + 1) * N_ + i0 + 8] = oacc[nt2][3] * inv1;
    }
}

// ---------------------------------------------------------------------------
// Launch
// ---------------------------------------------------------------------------
extern "C" void kernel_launch(void* const* d_in, const int* in_sizes, int n_in,
                              void* d_out, int out_size)
{
    const float* x      = (const float*)d_in[0];
    const float* w_qkv  = (const float*)d_in[1];
    const float* w_out  = (const float*)d_in[2];
    const float* b_out  = (const float*)d_in[3];
    const float* temper = (const float*)d_in[4];
    const float* g1     = (const float*)d_in[5];
    const float* beta1  = (const float*)d_in[6];
    const float* g2     = (const float*)d_in[7];
    const float* beta2  = (const float*)d_in[8];
    const float* w_mlp1 = (const float*)d_in[9];
    const float* b_mlp1 = (const float*)d_in[10];
    const float* w_mlp2 = (const float*)d_in[11];
    const float* b_mlp2 = (const float*)d_in[12];
    float* outp = (float*)d_out;

    float *xn, *qkv, *qkT, *att, *x2, *y, *hb;
    cudaGetSymbolAddress((void**)&xn,  g_xn);
    cudaGetSymbolAddress((void**)&qkv, g_qkv);
    cudaGetSymbolAddress((void**)&qkT, g_qkT);
    cudaGetSymbolAddress((void**)&att, g_att);
    cudaGetSymbolAddress((void**)&x2,  g_x2);
    cudaGetSymbolAddress((void**)&y,   g_y);
    cudaGetSymbolAddress((void**)&hb,  g_h);

    // 1) GroupNorm 1
    groupnorm_k<<<dim3(GROUPS, B_), 256>>>(x, g1, beta1, xn);
    // 2) QKV 1x1 conv
    sgemm_k<false, false, false><<<dim3(N_ / 64, (3 * C_) / 64, B_), 256>>>(
        w_qkv, xn, nullptr, nullptr, qkv, 3 * C_, C_, N_);
    // 2b) transpose q,k to token-major
    transpose_qk<<<dim3(N_ / 32, HEADS, 2 * B_), dim3(32, 8)>>>(qkv, qkT);
    // 3) Attention (mma.sync: tf32 QK^T, bf16 PV)
    flash_mma<<<dim3(N_ / 64, HEADS, B_), 128>>>(qkT, qkv, temper, att);
    // 4) Out-proj + bias + residual(x)
    sgemm_k<true, true, false><<<dim3(N_ / 64, C_ / 64, B_), 256>>>(
        w_out, att, b_out, x, x2, C_, C_, N_);
    // 5) GroupNorm 2
    groupnorm_k<<<dim3(GROUPS, B_), 256>>>(x2, g2, beta2, y);
    // 6) MLP1 + bias + gelu
    sgemm_k<true, false, true><<<dim3(N_ / 64, HID / 64, B_), 256>>>(
        w_mlp1, y, b_mlp1, nullptr, hb, HID, C_, N_);
    // 7) MLP2 + bias + residual(x2) -> output
    sgemm_k<true, true, false><<<dim3(N_ / 64, C_ / 64, B_), 256>>>(
        w_mlp2, hb, b_mlp2, x2, outp, C_, HID, N_);
}

// round 9
// speedup vs baseline: 1.0026x; 1.0002x over previous
#include <cuda_runtime.h>
#include <cuda_bf16.h>
#include <math.h>
#include <stdint.h>

// ---------------------------------------------------------------------------
// Problem constants
// ---------------------------------------------------------------------------
#define B_     2
#define C_     256
#define N_     4096          // H*W = 64*64
#define HEADS  8
#define HD     32            // C_/HEADS
#define GROUPS 32
#define CPG    8             // C_/GROUPS
#define HID    64            // C_/4
#define EPSF   1e-5f

// ---------------------------------------------------------------------------
// Scratch (static device globals; no allocation allowed)
// ---------------------------------------------------------------------------
__device__ float g_xn [B_ * C_ * N_];        // GN1 output
__device__ float g_qkv[B_ * 3 * C_ * N_];    // qkv  [b][3C][N]
__device__ float g_qkT[B_ * 2 * C_ * N_];    // q,k transposed: [b*2+p][h][i][d]
__device__ float g_att[B_ * C_ * N_];        // attention output (pre-proj)
__device__ float g_x2 [B_ * C_ * N_];        // identity + out-proj
__device__ float g_y  [B_ * C_ * N_];        // GN2 output
__device__ float g_h  [B_ * HID * N_];       // mlp hidden (post gelu)

// ---------------------------------------------------------------------------
// small helpers
// ---------------------------------------------------------------------------
__device__ __forceinline__ float ex2f(float x) {
    float y; asm("ex2.approx.ftz.f32 %0, %1;" : "=f"(y) : "f"(x)); return y;
}
__device__ __forceinline__ uint32_t pkbf(float lo, float hi) {
    uint32_t r; asm("cvt.rn.bf16x2.f32 %0, %1, %2;" : "=r"(r) : "f"(hi), "f"(lo));
    return r;
}
// m16n8k8 tf32 mma, D += A*B
__device__ __forceinline__ void mma_tf32(float* d, const uint32_t* a,
                                         uint32_t b0, uint32_t b1) {
    asm volatile("mma.sync.aligned.m16n8k8.row.col.f32.tf32.tf32.f32 "
        "{%0,%1,%2,%3}, {%4,%5,%6,%7}, {%8,%9}, {%0,%1,%2,%3};"
        : "+f"(d[0]), "+f"(d[1]), "+f"(d[2]), "+f"(d[3])
        : "r"(a[0]), "r"(a[1]), "r"(a[2]), "r"(a[3]), "r"(b0), "r"(b1));
}
// m16n8k16 bf16 mma, D += A*B
__device__ __forceinline__ void mma_bf16(float* d, uint32_t a0, uint32_t a1,
                                         uint32_t a2, uint32_t a3,
                                         uint32_t b0, uint32_t b1) {
    asm volatile("mma.sync.aligned.m16n8k16.row.col.f32.bf16.bf16.f32 "
        "{%0,%1,%2,%3}, {%4,%5,%6,%7}, {%8,%9}, {%0,%1,%2,%3};"
        : "+f"(d[0]), "+f"(d[1]), "+f"(d[2]), "+f"(d[3])
        : "r"(a0), "r"(a1), "r"(a2), "r"(a3), "r"(b0), "r"(b1));
}

// ---------------------------------------------------------------------------
// GroupNorm
// ---------------------------------------------------------------------------
__global__ void __launch_bounds__(256) groupnorm_k(
    const float* __restrict__ x, const float* __restrict__ gamma,
    const float* __restrict__ beta, float* __restrict__ out)
{
    const int g = blockIdx.x;
    const int b = blockIdx.y;
    const size_t base = ((size_t)b * C_ + (size_t)g * CPG) * N_;
    const float4* x4 = reinterpret_cast<const float4*>(x + base);
    float4* o4 = reinterpret_cast<float4*>(out + base);

    float s = 0.f, ss = 0.f;
    for (int i = threadIdx.x; i < (CPG * N_) / 4; i += 256) {
        float4 v = x4[i];
        s  += v.x + v.y + v.z + v.w;
        ss += v.x * v.x + v.y * v.y + v.z * v.z + v.w * v.w;
    }
    __shared__ float rs[8], rss[8];
    #pragma unroll
    for (int o = 16; o > 0; o >>= 1) {
        s  += __shfl_xor_sync(0xffffffffu, s,  o);
        ss += __shfl_xor_sync(0xffffffffu, ss, o);
    }
    int wid = threadIdx.x >> 5;
    if ((threadIdx.x & 31) == 0) { rs[wid] = s; rss[wid] = ss; }
    __syncthreads();
    __shared__ float s_mean, s_rstd;
    if (threadIdx.x == 0) {
        float ts = 0.f, tss = 0.f;
        #pragma unroll
        for (int i = 0; i < 8; i++) { ts += rs[i]; tss += rss[i]; }
        float inv_n = 1.f / (float)(CPG * N_);
        float mean = ts * inv_n;
        float var  = tss * inv_n - mean * mean;
        s_mean = mean;
        s_rstd = rsqrtf(var + EPSF);
    }
    __syncthreads();
    float mean = s_mean, rstd = s_rstd;

    for (int i = threadIdx.x; i < (CPG * N_) / 4; i += 256) {
        int c = g * CPG + (i >> 10);
        float ga = gamma[c] * rstd;
        float be = beta[c] - mean * ga;
        float4 v = x4[i];
        v.x = v.x * ga + be; v.y = v.y * ga + be;
        v.z = v.z * ga + be; v.w = v.w * ga + be;
        o4[i] = v;
    }
}

// ---------------------------------------------------------------------------
// Tiled SGEMM (fp32)
// ---------------------------------------------------------------------------
template<bool BIAS, bool RES, bool GELU>
__global__ void __launch_bounds__(256) sgemm_k(
    const float* __restrict__ W, const float* __restrict__ X,
    const float* __restrict__ bias, const float* __restrict__ res,
    float* __restrict__ out, int M, int K, int NN)
{
    __shared__ float Ws[16][64];
    __shared__ float Xs[16][64];

    const int bz = blockIdx.z;
    const int m0 = blockIdx.y * 64;
    const int n0 = blockIdx.x * 64;
    const int tid = threadIdx.x;
    const int tn = tid & 15;
    const int tm = tid >> 4;

    const float* Xb = X + (size_t)bz * K * NN;

    float acc[4][4];
    #pragma unroll
    for (int i = 0; i < 4; i++)
        #pragma unroll
        for (int j = 0; j < 4; j++) acc[i][j] = 0.f;

    const int wr  = tid >> 2;
    const int wc4 = tid & 3;
    const int xr  = tid >> 4;
    const int xc4 = tid & 15;

    for (int k0 = 0; k0 < K; k0 += 16) {
        float4 wv = *reinterpret_cast<const float4*>(
            W + (size_t)(m0 + wr) * K + k0 + 4 * wc4);
        Ws[4 * wc4 + 0][wr] = wv.x;
        Ws[4 * wc4 + 1][wr] = wv.y;
        Ws[4 * wc4 + 2][wr] = wv.z;
        Ws[4 * wc4 + 3][wr] = wv.w;
        *reinterpret_cast<float4*>(&Xs[xr][4 * xc4]) =
            *reinterpret_cast<const float4*>(Xb + (size_t)(k0 + xr) * NN + n0 + 4 * xc4);
        __syncthreads();

        #pragma unroll
        for (int kk = 0; kk < 16; kk++) {
            float4 wf = *reinterpret_cast<const float4*>(&Ws[kk][4 * tm]);
            float4 xf = *reinterpret_cast<const float4*>(&Xs[kk][4 * tn]);
            float wa[4] = {wf.x, wf.y, wf.z, wf.w};
            float xa[4] = {xf.x, xf.y, xf.z, xf.w};
            #pragma unroll
            for (int i = 0; i < 4; i++)
                #pragma unroll
                for (int j = 0; j < 4; j++)
                    acc[i][j] = fmaf(wa[i], xa[j], acc[i][j]);
        }
        __syncthreads();
    }

    #pragma unroll
    for (int i = 0; i < 4; i++) {
        int m = m0 + 4 * tm + i;
        size_t row = ((size_t)bz * M + m) * NN + n0 + 4 * tn;
        float bv = BIAS ? bias[m] : 0.f;
        float4 v;
        float tmpv[4];
        #pragma unroll
        for (int j = 0; j < 4; j++) {
            float t = acc[i][j] + bv;
            if (GELU) t = 0.5f * t * (1.f + erff(t * 0.70710678118654752f));
            tmpv[j] = t;
        }
        if (RES) {
            float4 r = *reinterpret_cast<const float4*>(res + row);
            tmpv[0] += r.x; tmpv[1] += r.y; tmpv[2] += r.z; tmpv[3] += r.w;
        }
        v.x = tmpv[0]; v.y = tmpv[1]; v.z = tmpv[2]; v.w = tmpv[3];
        *reinterpret_cast<float4*>(out + row) = v;
    }
}

// ---------------------------------------------------------------------------
// Transpose q,k parts of qkv: [b][p*256 + h*32 + d][i] -> qkT[(b*2+p)][h][i][d]
// ---------------------------------------------------------------------------
__global__ void __launch_bounds__(256) transpose_qk(
    const float* __restrict__ qkv, float* __restrict__ qkT)
{
    __shared__ float tile[32][33];
    const int i0 = blockIdx.x * 32;
    const int h  = blockIdx.y;
    const int z  = blockIdx.z;         // b*2 + p
    const int b  = z >> 1, p = z & 1;
    const float* src = qkv + ((size_t)b * 3 * C_ + (size_t)p * C_ + (size_t)h * HD) * N_ + i0;
    #pragma unroll
    for (int k = 0; k < 4; k++) {
        int c = threadIdx.y + 8 * k;
        tile[c][threadIdx.x] = src[(size_t)c * N_ + threadIdx.x];
    }
    __syncthreads();
    float* dst = qkT + (((size_t)z * HEADS + h) * N_ + i0) * HD;
    #pragma unroll
    for (int k = 0; k < 4; k++) {
        int r = threadIdx.y + 8 * k;
        dst[(size_t)r * HD + threadIdx.x] = tile[threadIdx.x][r];
    }
}

// ---------------------------------------------------------------------------
// Flash attention via mma.sync (tf32 QK^T, bf16 P*V).
// CTA = (b, h, 64-query tile); 4 warps, warp w owns query rows q0+16w..+15.
// Key tiles of 64. K smem rows padded to 36 words; V smem (bf16) rows padded
// to 36 words -> conflict-free fragment LDS (bank = 4*(lane>>2)+(lane&3)).
// Online softmax in log2 domain (Q pre-scaled by temp*log2(e)).
// ---------------------------------------------------------------------------
__global__ void __launch_bounds__(128) flash_mma(
    const float* __restrict__ qkT, const float* __restrict__ qkv,
    const float* __restrict__ temp, float* __restrict__ out)
{
    __shared__ float    Ks[64 * 36];     // K tile [64 keys][32 d], pad 36
    __shared__ uint32_t Vs[32 * 36];     // V tile [32 d][64 keys] bf16x2, pad 36 words

    const int tid  = threadIdx.x;
    const int lane = tid & 31;
    const int w    = tid >> 5;
    const int b    = blockIdx.z;
    const int h    = blockIdx.y;
    const int q0   = blockIdx.x * 64;

    const float* qTb = qkT + ((size_t)(b * 2 + 0) * HEADS + h) * N_ * HD;
    const float* kTb = qkT + ((size_t)(b * 2 + 1) * HEADS + h) * N_ * HD;
    const float* vb  = qkv + ((size_t)b * 3 * C_ + 2 * C_ + (size_t)h * HD) * N_;

    const float ts2 = fminf(fmaxf(temp[h], 1e-4f), 10.0f) * 1.4426950408889634f;

    // ---- stage Q tile [64 x 32] (scaled) into Ks, then lift to A-fragments ----
    {
        const float4* src = reinterpret_cast<const float4*>(qTb + (size_t)q0 * HD);
        #pragma unroll
        for (int k = 0; k < 4; k++) {
            int f = tid + 128 * k;              // 512 float4 total
            float4 v = src[f];
            v.x *= ts2; v.y *= ts2; v.z *= ts2; v.w *= ts2;
            *reinterpret_cast<float4*>(&Ks[(f >> 3) * 36 + (f & 7) * 4]) = v;
        }
    }
    __syncthreads();
    uint32_t qa[4][4];
    {
        const int r = lane >> 2, c = lane & 3;
        #pragma unroll
        for (int kt = 0; kt < 4; kt++) {
            qa[kt][0] = __float_as_uint(Ks[(16 * w + r)     * 36 + c     + 8 * kt]);
            qa[kt][1] = __float_as_uint(Ks[(16 * w + r + 8) * 36 + c     + 8 * kt]);
            qa[kt][2] = __float_as_uint(Ks[(16 * w + r)     * 36 + c + 4 + 8 * kt]);
            qa[kt][3] = __float_as_uint(Ks[(16 * w + r + 8) * 36 + c + 4 + 8 * kt]);
        }
    }

    float oacc[4][4];
    #pragma unroll
    for (int i = 0; i < 4; i++)
        #pragma unroll
        for (int j = 0; j < 4; j++) oacc[i][j] = 0.f;
    float m0 = -INFINITY, m1 = -INFINITY, l0 = 0.f, l1 = 0.f;

    // ---- prefetch tile 0 ----
    float4 kreg[4], vreg[4];
    {
        const float4* ks = reinterpret_cast<const float4*>(kTb);
        #pragma unroll
        for (int k = 0; k < 4; k++) kreg[k] = ks[tid + 128 * k];
        #pragma unroll
        for (int k = 0; k < 4; k++) {
            int idx = tid + 128 * k;
            vreg[k] = *reinterpret_cast<const float4*>(
                vb + (size_t)(idx >> 4) * N_ + (idx & 15) * 4);
        }
    }

    for (int t = 0; t < N_ / 64; t++) {
        __syncthreads();   // previous tile fully consumed (and Q frags lifted)
        // ---- store staged tile ----
        #pragma unroll
        for (int k = 0; k < 4; k++) {
            int idx = tid + 128 * k;
            *reinterpret_cast<float4*>(&Ks[(idx >> 3) * 36 + (idx & 7) * 4]) = kreg[k];
        }
        #pragma unroll
        for (int k = 0; k < 4; k++) {
            int idx = tid + 128 * k;
            int row = idx >> 4, c4 = idx & 15;
            Vs[row * 36 + 2 * c4]     = pkbf(vreg[k].x, vreg[k].y);
            Vs[row * 36 + 2 * c4 + 1] = pkbf(vreg[k].z, vreg[k].w);
        }
        __syncthreads();

        // ---- prefetch next tile ----
        if (t + 1 < N_ / 64) {
            const int j0 = (t + 1) * 64;
            const float4* ks = reinterpret_cast<const float4*>(kTb + (size_t)j0 * HD);
            #pragma unroll
            for (int k = 0; k < 4; k++) kreg[k] = ks[tid + 128 * k];
            #pragma unroll
            for (int k = 0; k < 4; k++) {
                int idx = tid + 128 * k;
                vreg[k] = *reinterpret_cast<const float4*>(
                    vb + (size_t)(idx >> 4) * N_ + j0 + (idx & 15) * 4);
            }
        }

        const int r = lane >> 2, c = lane & 3;

        // ---- S = Q K^T (tf32) : 8 n-tiles x 4 k-tiles ----
        float sacc[8][4];
        #pragma unroll
        for (int nt = 0; nt < 8; nt++)
            #pragma unroll
            for (int j = 0; j < 4; j++) sacc[nt][j] = 0.f;
        #pragma unroll
        for (int kt = 0; kt < 4; kt++) {
            #pragma unroll
            for (int nt = 0; nt < 8; nt++) {
                uint32_t b0 = __float_as_uint(Ks[(r + 8 * nt) * 36 + c     + 8 * kt]);
                uint32_t b1 = __float_as_uint(Ks[(r + 8 * nt) * 36 + c + 4 + 8 * kt]);
                mma_tf32(sacc[nt], qa[kt], b0, b1);
            }
        }

        // ---- online softmax (log2 domain) ----
        float t0 = -INFINITY, t1 = -INFINITY;
        #pragma unroll
        for (int nt = 0; nt < 8; nt++) {
            t0 = fmaxf(t0, fmaxf(sacc[nt][0], sacc[nt][1]));
            t1 = fmaxf(t1, fmaxf(sacc[nt][2], sacc[nt][3]));
        }
        t0 = fmaxf(t0, __shfl_xor_sync(0xffffffffu, t0, 1));
        t0 = fmaxf(t0, __shfl_xor_sync(0xffffffffu, t0, 2));
        t1 = fmaxf(t1, __shfl_xor_sync(0xffffffffu, t1, 1));
        t1 = fmaxf(t1, __shfl_xor_sync(0xffffffffu, t1, 2));
        float mn0 = fmaxf(m0, t0), mn1 = fmaxf(m1, t1);
        float corr0 = ex2f(m0 - mn0), corr1 = ex2f(m1 - mn1);
        m0 = mn0; m1 = mn1;

        float ls0 = 0.f, ls1 = 0.f;
        #pragma unroll
        for (int nt = 0; nt < 8; nt++) {
            sacc[nt][0] = ex2f(sacc[nt][0] - mn0);
            sacc[nt][1] = ex2f(sacc[nt][1] - mn0);
            sacc[nt][2] = ex2f(sacc[nt][2] - mn1);
            sacc[nt][3] = ex2f(sacc[nt][3] - mn1);
            ls0 += sacc[nt][0] + sacc[nt][1];
            ls1 += sacc[nt][2] + sacc[nt][3];
        }
        ls0 += __shfl_xor_sync(0xffffffffu, ls0, 1);
        ls0 += __shfl_xor_sync(0xffffffffu, ls0, 2);
        ls1 += __shfl_xor_sync(0xffffffffu, ls1, 1);
        ls1 += __shfl_xor_sync(0xffffffffu, ls1, 2);
        l0 = l0 * corr0 + ls0;
        l1 = l1 * corr1 + ls1;
        #pragma unroll
        for (int nt2 = 0; nt2 < 4; nt2++) {
            oacc[nt2][0] *= corr0; oacc[nt2][1] *= corr0;
            oacc[nt2][2] *= corr1; oacc[nt2][3] *= corr1;
        }

        // ---- O += P V (bf16) : P frags straight from S accumulators ----
        #pragma unroll
        for (int kt = 0; kt < 4; kt++) {
            uint32_t a0 = pkbf(sacc[2 * kt][0],     sacc[2 * kt][1]);
            uint32_t a1 = pkbf(sacc[2 * kt][2],     sacc[2 * kt][3]);
            uint32_t a2 = pkbf(sacc[2 * kt + 1][0], sacc[2 * kt + 1][1]);
            uint32_t a3 = pkbf(sacc[2 * kt + 1][2], sacc[2 * kt + 1][3]);
            #pragma unroll
            for (int nt2 = 0; nt2 < 4; nt2++) {
                uint32_t b0 = Vs[(r + 8 * nt2) * 36 + c + 8 * kt];
                uint32_t b1 = Vs[(r + 8 * nt2) * 36 + c + 8 * kt + 4];
                mma_bf16(oacc[nt2], a0, a1, a2, a3, b0, b1);
            }
        }
    }

    // ---- write out: att[(b*C + h*32 + d)*N + i] ----
    const float inv0 = 1.f / l0, inv1 = 1.f / l1;
    const int r = lane >> 2, c = lane & 3;
    const int i0 = q0 + 16 * w + r;
    float* ob = out + ((size_t)b * C_ + (size_t)h * HD) * N_;
    #pragma unroll
    for (int nt2 = 0; nt2 < 4; nt2++) {
        int d = 8 * nt2 + 2 * c;
        ob[(size_t)d       * N_ + i0]     = oacc[nt2][0] * inv0;
        ob[(size_t)(d + 1) * N_ + i0]     = oacc[nt2][1] * inv0;
        ob[(size_t)d       * N_ + i0 + 8] = oacc[nt2][2] * inv1;
        ob[(size_t)(d + 1) * N_ + i0 + 8] = oacc[nt2][3] * inv1;
    }
}

// ---------------------------------------------------------------------------
// Launch
// ---------------------------------------------------------------------------
extern "C" void kernel_launch(void* const* d_in, const int* in_sizes, int n_in,
                              void* d_out, int out_size)
{
    const float* x      = (const float*)d_in[0];
    const float* w_qkv  = (const float*)d_in[1];
    const float* w_out  = (const float*)d_in[2];
    const float* b_out  = (const float*)d_in[3];
    const float* temper = (const float*)d_in[4];
    const float* g1     = (const float*)d_in[5];
    const float* beta1  = (const float*)d_in[6];
    const float* g2     = (const float*)d_in[7];
    const float* beta2  = (const float*)d_in[8];
    const float* w_mlp1 = (const float*)d_in[9];
    const float* b_mlp1 = (const float*)d_in[10];
    const float* w_mlp2 = (const float*)d_in[11];
    const float* b_mlp2 = (const float*)d_in[12];
    float* outp = (float*)d_out;

    float *xn, *qkv, *qkT, *att, *x2, *y, *hb;
    cudaGetSymbolAddress((void**)&xn,  g_xn);
    cudaGetSymbolAddress((void**)&qkv, g_qkv);
    cudaGetSymbolAddress((void**)&qkT, g_qkT);
    cudaGetSymbolAddress((void**)&att, g_att);
    cudaGetSymbolAddress((void**)&x2,  g_x2);
    cudaGetSymbolAddress((void**)&y,   g_y);
    cudaGetSymbolAddress((void**)&hb,  g_h);

    // 1) GroupNorm 1
    groupnorm_k<<<dim3(GROUPS, B_), 256>>>(x, g1, beta1, xn);
    // 2) QKV 1x1 conv
    sgemm_k<false, false, false><<<dim3(N_ / 64, (3 * C_) / 64, B_), 256>>>(
        w_qkv, xn, nullptr, nullptr, qkv, 3 * C_, C_, N_);
    // 2b) transpose q,k to token-major
    transpose_qk<<<dim3(N_ / 32, HEADS, 2 * B_), dim3(32, 8)>>>(qkv, qkT);
    // 3) Attention (mma.sync: tf32 QK^T, bf16 PV)
    flash_mma<<<dim3(N_ / 64, HEADS, B_), 128>>>(qkT, qkv, temper, att);
    // 4) Out-proj + bias + residual(x)
    sgemm_k<true, true, false><<<dim3(N_ / 64, C_ / 64, B_), 256>>>(
        w_out, att, b_out, x, x2, C_, C_, N_);
    // 5) GroupNorm 2
    groupnorm_k<<<dim3(GROUPS, B_), 256>>>(x2, g2, beta2, y);
    // 6) MLP1 + bias + gelu
    sgemm_k<true, false, true><<<dim3(N_ / 64, HID / 64, B_), 256>>>(
        w_mlp1, y, b_mlp1, nullptr, hb, HID, C_, N_);
    // 7) MLP2 + bias + residual(x2) -> output
    sgemm_k<true, true, false><<<dim3(N_ / 64, C_ / 64, B_), 256>>>(
        w_mlp2, hb, b_mlp2, x2, outp, C_, HID, N_);
}

// round 10
// speedup vs baseline: 1.0066x; 1.0040x over previous
#include <cuda_runtime.h>
#include <cuda_bf16.h>
#include <math.h>
#include <stdint.h>

// ---------------------------------------------------------------------------
// Problem constants
// ---------------------------------------------------------------------------
#define B_     2
#define C_     256
#define N_     4096          // H*W = 64*64
#define HEADS  8
#define HD     32            // C_/HEADS
#define GROUPS 32
#define CPG    8             // C_/GROUPS
#define HID    64            // C_/4
#define EPSF   1e-5f

// ---------------------------------------------------------------------------
// Scratch (static device globals; no allocation allowed)
// ---------------------------------------------------------------------------
__device__ float g_xn [B_ * C_ * N_];        // GN1 output
__device__ float g_qkv[B_ * 3 * C_ * N_];    // qkv  [b][3C][N]
__device__ float g_qkT[B_ * 2 * C_ * N_];    // q,k transposed: [b*2+p][h][i][d]
__device__ float g_att[B_ * C_ * N_];        // attention output (pre-proj)
__device__ float g_x2 [B_ * C_ * N_];        // identity + out-proj
__device__ float g_y  [B_ * C_ * N_];        // GN2 output
__device__ float g_h  [B_ * HID * N_];       // mlp hidden (post gelu)

// ---------------------------------------------------------------------------
// small helpers
// ---------------------------------------------------------------------------
__device__ __forceinline__ float ex2f(float x) {
    float y; asm("ex2.approx.ftz.f32 %0, %1;" : "=f"(y) : "f"(x)); return y;
}
__device__ __forceinline__ uint32_t pkbf(float lo, float hi) {
    uint32_t r; asm("cvt.rn.bf16x2.f32 %0, %1, %2;" : "=r"(r) : "f"(hi), "f"(lo));
    return r;
}
// m16n8k8 tf32 mma, D += A*B
__device__ __forceinline__ void mma_tf32(float* d, const uint32_t* a,
                                         uint32_t b0, uint32_t b1) {
    asm volatile("mma.sync.aligned.m16n8k8.row.col.f32.tf32.tf32.f32 "
        "{%0,%1,%2,%3}, {%4,%5,%6,%7}, {%8,%9}, {%0,%1,%2,%3};"
        : "+f"(d[0]), "+f"(d[1]), "+f"(d[2]), "+f"(d[3])
        : "r"(a[0]), "r"(a[1]), "r"(a[2]), "r"(a[3]), "r"(b0), "r"(b1));
}
// m16n8k16 bf16 mma, D += A*B
__device__ __forceinline__ void mma_bf16(float* d, uint32_t a0, uint32_t a1,
                                         uint32_t a2, uint32_t a3,
                                         uint32_t b0, uint32_t b1) {
    asm volatile("mma.sync.aligned.m16n8k16.row.col.f32.bf16.bf16.f32 "
        "{%0,%1,%2,%3}, {%4,%5,%6,%7}, {%8,%9}, {%0,%1,%2,%3};"
        : "+f"(d[0]), "+f"(d[1]), "+f"(d[2]), "+f"(d[3])
        : "r"(a0), "r"(a1), "r"(a2), "r"(a3), "r"(b0), "r"(b1));
}

// ---------------------------------------------------------------------------
// GroupNorm
// ---------------------------------------------------------------------------
__global__ void __launch_bounds__(256) groupnorm_k(
    const float* __restrict__ x, const float* __restrict__ gamma,
    const float* __restrict__ beta, float* __restrict__ out)
{
    const int g = blockIdx.x;
    const int b = blockIdx.y;
    const size_t base = ((size_t)b * C_ + (size_t)g * CPG) * N_;
    const float4* x4 = reinterpret_cast<const float4*>(x + base);
    float4* o4 = reinterpret_cast<float4*>(out + base);

    float s = 0.f, ss = 0.f;
    for (int i = threadIdx.x; i < (CPG * N_) / 4; i += 256) {
        float4 v = x4[i];
        s  += v.x + v.y + v.z + v.w;
        ss += v.x * v.x + v.y * v.y + v.z * v.z + v.w * v.w;
    }
    __shared__ float rs[8], rss[8];
    #pragma unroll
    for (int o = 16; o > 0; o >>= 1) {
        s  += __shfl_xor_sync(0xffffffffu, s,  o);
        ss += __shfl_xor_sync(0xffffffffu, ss, o);
    }
    int wid = threadIdx.x >> 5;
    if ((threadIdx.x & 31) == 0) { rs[wid] = s; rss[wid] = ss; }
    __syncthreads();
    __shared__ float s_mean, s_rstd;
    if (threadIdx.x == 0) {
        float ts = 0.f, tss = 0.f;
        #pragma unroll
        for (int i = 0; i < 8; i++) { ts += rs[i]; tss += rss[i]; }
        float inv_n = 1.f / (float)(CPG * N_);
        float mean = ts * inv_n;
        float var  = tss * inv_n - mean * mean;
        s_mean = mean;
        s_rstd = rsqrtf(var + EPSF);
    }
    __syncthreads();
    float mean = s_mean, rstd = s_rstd;

    for (int i = threadIdx.x; i < (CPG * N_) / 4; i += 256) {
        int c = g * CPG + (i >> 10);
        float ga = gamma[c] * rstd;
        float be = beta[c] - mean * ga;
        float4 v = x4[i];
        v.x = v.x * ga + be; v.y = v.y * ga + be;
        v.z = v.z * ga + be; v.w = v.w * ga + be;
        o4[i] = v;
    }
}

// ---------------------------------------------------------------------------
// Tiled SGEMM (fp32)
// ---------------------------------------------------------------------------
template<bool BIAS, bool RES, bool GELU>
__global__ void __launch_bounds__(256) sgemm_k(
    const float* __restrict__ W, const float* __restrict__ X,
    const float* __restrict__ bias, const float* __restrict__ res,
    float* __restrict__ out, int M, int K, int NN)
{
    __shared__ float Ws[16][64];
    __shared__ float Xs[16][64];

    const int bz = blockIdx.z;
    const int m0 = blockIdx.y * 64;
    const int n0 = blockIdx.x * 64;
    const int tid = threadIdx.x;
    const int tn = tid & 15;
    const int tm = tid >> 4;

    const float* Xb = X + (size_t)bz * K * NN;

    float acc[4][4];
    #pragma unroll
    for (int i = 0; i < 4; i++)
        #pragma unroll
        for (int j = 0; j < 4; j++) acc[i][j] = 0.f;

    const int wr  = tid >> 2;
    const int wc4 = tid & 3;
    const int xr  = tid >> 4;
    const int xc4 = tid & 15;

    for (int k0 = 0; k0 < K; k0 += 16) {
        float4 wv = *reinterpret_cast<const float4*>(
            W + (size_t)(m0 + wr) * K + k0 + 4 * wc4);
        Ws[4 * wc4 + 0][wr] = wv.x;
        Ws[4 * wc4 + 1][wr] = wv.y;
        Ws[4 * wc4 + 2][wr] = wv.z;
        Ws[4 * wc4 + 3][wr] = wv.w;
        *reinterpret_cast<float4*>(&Xs[xr][4 * xc4]) =
            *reinterpret_cast<const float4*>(Xb + (size_t)(k0 + xr) * NN + n0 + 4 * xc4);
        __syncthreads();

        #pragma unroll
        for (int kk = 0; kk < 16; kk++) {
            float4 wf = *reinterpret_cast<const float4*>(&Ws[kk][4 * tm]);
            float4 xf = *reinterpret_cast<const float4*>(&Xs[kk][4 * tn]);
            float wa[4] = {wf.x, wf.y, wf.z, wf.w};
            float xa[4] = {xf.x, xf.y, xf.z, xf.w};
            #pragma unroll
            for (int i = 0; i < 4; i++)
                #pragma unroll
                for (int j = 0; j < 4; j++)
                    acc[i][j] = fmaf(wa[i], xa[j], acc[i][j]);
        }
        __syncthreads();
    }

    #pragma unroll
    for (int i = 0; i < 4; i++) {
        int m = m0 + 4 * tm + i;
        size_t row = ((size_t)bz * M + m) * NN + n0 + 4 * tn;
        float bv = BIAS ? bias[m] : 0.f;
        float4 v;
        float tmpv[4];
        #pragma unroll
        for (int j = 0; j < 4; j++) {
            float t = acc[i][j] + bv;
            if (GELU) t = 0.5f * t * (1.f + erff(t * 0.70710678118654752f));
            tmpv[j] = t;
        }
        if (RES) {
            float4 r = *reinterpret_cast<const float4*>(res + row);
            tmpv[0] += r.x; tmpv[1] += r.y; tmpv[2] += r.z; tmpv[3] += r.w;
        }
        v.x = tmpv[0]; v.y = tmpv[1]; v.z = tmpv[2]; v.w = tmpv[3];
        *reinterpret_cast<float4*>(out + row) = v;
    }
}

// ---------------------------------------------------------------------------
// Transpose q,k parts of qkv: [b][p*256 + h*32 + d][i] -> qkT[(b*2+p)][h][i][d]
// ---------------------------------------------------------------------------
__global__ void __launch_bounds__(256) transpose_qk(
    const float* __restrict__ qkv, float* __restrict__ qkT)
{
    __shared__ float tile[32][33];
    const int i0 = blockIdx.x * 32;
    const int h  = blockIdx.y;
    const int z  = blockIdx.z;         // b*2 + p
    const int b  = z >> 1, p = z & 1;
    const float* src = qkv + ((size_t)b * 3 * C_ + (size_t)p * C_ + (size_t)h * HD) * N_ + i0;
    #pragma unroll
    for (int k = 0; k < 4; k++) {
        int c = threadIdx.y + 8 * k;
        tile[c][threadIdx.x] = src[(size_t)c * N_ + threadIdx.x];
    }
    __syncthreads();
    float* dst = qkT + (((size_t)z * HEADS + h) * N_ + i0) * HD;
    #pragma unroll
    for (int k = 0; k < 4; k++) {
        int r = threadIdx.y + 8 * k;
        dst[(size_t)r * HD + threadIdx.x] = tile[threadIdx.x][r];
    }
}

// ---------------------------------------------------------------------------
// Flash attention via mma.sync (tf32 QK^T, bf16 P*V).
// CTA = (b, h, 64-query tile); 4 warps, warp w owns query rows q0+16w..+15.
// Key tiles of 64. K smem rows padded to 36 words; V smem (bf16) rows padded
// to 36 words -> conflict-free fragment LDS (bank = 4*(lane>>2)+(lane&3)).
// Online softmax in log2 domain (Q pre-scaled by temp*log2(e)).
// ---------------------------------------------------------------------------
__global__ void __launch_bounds__(128) flash_mma(
    const float* __restrict__ qkT, const float* __restrict__ qkv,
    const float* __restrict__ temp, float* __restrict__ out)
{
    __shared__ float    Ks[64 * 36];     // K tile [64 keys][32 d], pad 36
    __shared__ uint32_t Vs[32 * 36];     // V tile [32 d][64 keys] bf16x2, pad 36 words

    const int tid  = threadIdx.x;
    const int lane = tid & 31;
    const int w    = tid >> 5;
    const int b    = blockIdx.z;
    const int h    = blockIdx.y;
    const int q0   = blockIdx.x * 64;

    const float* qTb = qkT + ((size_t)(b * 2 + 0) * HEADS + h) * N_ * HD;
    const float* kTb = qkT + ((size_t)(b * 2 + 1) * HEADS + h) * N_ * HD;
    const float* vb  = qkv + ((size_t)b * 3 * C_ + 2 * C_ + (size_t)h * HD) * N_;

    const float ts2 = fminf(fmaxf(temp[h], 1e-4f), 10.0f) * 1.4426950408889634f;

    // ---- stage Q tile [64 x 32] (scaled) into Ks, then lift to A-fragments ----
    {
        const float4* src = reinterpret_cast<const float4*>(qTb + (size_t)q0 * HD);
        #pragma unroll
        for (int k = 0; k < 4; k++) {
            int f = tid + 128 * k;              // 512 float4 total
            float4 v = src[f];
            v.x *= ts2; v.y *= ts2; v.z *= ts2; v.w *= ts2;
            *reinterpret_cast<float4*>(&Ks[(f >> 3) * 36 + (f & 7) * 4]) = v;
        }
    }
    __syncthreads();
    uint32_t qa[4][4];
    {
        const int r = lane >> 2, c = lane & 3;
        #pragma unroll
        for (int kt = 0; kt < 4; kt++) {
            qa[kt][0] = __float_as_uint(Ks[(16 * w + r)     * 36 + c     + 8 * kt]);
            qa[kt][1] = __float_as_uint(Ks[(16 * w + r + 8) * 36 + c     + 8 * kt]);
            qa[kt][2] = __float_as_uint(Ks[(16 * w + r)     * 36 + c + 4 + 8 * kt]);
            qa[kt][3] = __float_as_uint(Ks[(16 * w + r + 8) * 36 + c + 4 + 8 * kt]);
        }
    }

    float oacc[4][4];
    #pragma unroll
    for (int i = 0; i < 4; i++)
        #pragma unroll
        for (int j = 0; j < 4; j++) oacc[i][j] = 0.f;
    float m0 = -INFINITY, m1 = -INFINITY, l0 = 0.f, l1 = 0.f;

    // ---- prefetch tile 0 ----
    float4 kreg[4], vreg[4];
    {
        const float4* ks = reinterpret_cast<const float4*>(kTb);
        #pragma unroll
        for (int k = 0; k < 4; k++) kreg[k] = ks[tid + 128 * k];
        #pragma unroll
        for (int k = 0; k < 4; k++) {
            int idx = tid + 128 * k;
            vreg[k] = *reinterpret_cast<const float4*>(
                vb + (size_t)(idx >> 4) * N_ + (idx & 15) * 4);
        }
    }

    for (int t = 0; t < N_ / 64; t++) {
        __syncthreads();   // previous tile fully consumed (and Q frags lifted)
        // ---- store staged tile ----
        #pragma unroll
        for (int k = 0; k < 4; k++) {
            int idx = tid + 128 * k;
            *reinterpret_cast<float4*>(&Ks[(idx >> 3) * 36 + (idx & 7) * 4]) = kreg[k];
        }
        #pragma unroll
        for (int k = 0; k < 4; k++) {
            int idx = tid + 128 * k;
            int row = idx >> 4, c4 = idx & 15;
            Vs[row * 36 + 2 * c4]     = pkbf(vreg[k].x, vreg[k].y);
            Vs[row * 36 + 2 * c4 + 1] = pkbf(vreg[k].z, vreg[k].w);
        }
        __syncthreads();

        // ---- prefetch next tile ----
        if (t + 1 < N_ / 64) {
            const int j0 = (t + 1) * 64;
            const float4* ks = reinterpret_cast<const float4*>(kTb + (size_t)j0 * HD);
            #pragma unroll
            for (int k = 0; k < 4; k++) kreg[k] = ks[tid + 128 * k];
            #pragma unroll
            for (int k = 0; k < 4; k++) {
                int idx = tid + 128 * k;
                vreg[k] = *reinterpret_cast<const float4*>(
                    vb + (size_t)(idx >> 4) * N_ + j0 + (idx & 15) * 4);
            }
        }

        const int r = lane >> 2, c = lane & 3;

        // ---- S = Q K^T (tf32) : 8 n-tiles x 4 k-tiles ----
        float sacc[8][4];
        #pragma unroll
        for (int nt = 0; nt < 8; nt++)
            #pragma unroll
            for (int j = 0; j < 4; j++) sacc[nt][j] = 0.f;
        #pragma unroll
        for (int kt = 0; kt < 4; kt++) {
            #pragma unroll
            for (int nt = 0; nt < 8; nt++) {
                uint32_t b0 = __float_as_uint(Ks[(r + 8 * nt) * 36 + c     + 8 * kt]);
                uint32_t b1 = __float_as_uint(Ks[(r + 8 * nt) * 36 + c + 4 + 8 * kt]);
                mma_tf32(sacc[nt], qa[kt], b0, b1);
            }
        }

        // ---- online softmax (log2 domain) ----
        float t0 = -INFINITY, t1 = -INFINITY;
        #pragma unroll
        for (int nt = 0; nt < 8; nt++) {
            t0 = fmaxf(t0, fmaxf(sacc[nt][0], sacc[nt][1]));
            t1 = fmaxf(t1, fmaxf(sacc[nt][2], sacc[nt][3]));
        }
        t0 = fmaxf(t0, __shfl_xor_sync(0xffffffffu, t0, 1));
        t0 = fmaxf(t0, __shfl_xor_sync(0xffffffffu, t0, 2));
        t1 = fmaxf(t1, __shfl_xor_sync(0xffffffffu, t1, 1));
        t1 = fmaxf(t1, __shfl_xor_sync(0xffffffffu, t1, 2));
        float mn0 = fmaxf(m0, t0), mn1 = fmaxf(m1, t1);
        float corr0 = ex2f(m0 - mn0), corr1 = ex2f(m1 - mn1);
        m0 = mn0; m1 = mn1;

        float ls0 = 0.f, ls1 = 0.f;
        #pragma unroll
        for (int nt = 0; nt < 8; nt++) {
            sacc[nt][0] = ex2f(sacc[nt][0] - mn0);
            sacc[nt][1] = ex2f(sacc[nt][1] - mn0);
            sacc[nt][2] = ex2f(sacc[nt][2] - mn1);
            sacc[nt][3] = ex2f(sacc[nt][3] - mn1);
            ls0 += sacc[nt][0] + sacc[nt][1];
            ls1 += sacc[nt][2] + sacc[nt][3];
        }
        ls0 += __shfl_xor_sync(0xffffffffu, ls0, 1);
        ls0 += __shfl_xor_sync(0xffffffffu, ls0, 2);
        ls1 += __shfl_xor_sync(0xffffffffu, ls1, 1);
        ls1 += __shfl_xor_sync(0xffffffffu, ls1, 2);
        l0 = l0 * corr0 + ls0;
        l1 = l1 * corr1 + ls1;
        #pragma unroll
        for (int nt2 = 0; nt2 < 4; nt2++) {
            oacc[nt2][0] *= corr0; oacc[nt2][1] *= corr0;
            oacc[nt2][2] *= corr1; oacc[nt2][3] *= corr1;
        }

        // ---- O += P V (bf16) : P frags straight from S accumulators ----
        #pragma unroll
        for (int kt = 0; kt < 4; kt++) {
            uint32_t a0 = pkbf(sacc[2 * kt][0],     sacc[2 * kt][1]);
            uint32_t a1 = pkbf(sacc[2 * kt][2],     sacc[2 * kt][3]);
            uint32_t a2 = pkbf(sacc[2 * kt + 1][0], sacc[2 * kt + 1][1]);
            uint32_t a3 = pkbf(sacc[2 * kt + 1][2], sacc[2 * kt + 1][3]);
            #pragma unroll
            for (int nt2 = 0; nt2 < 4; nt2++) {
                uint32_t b0 = Vs[(r + 8 * nt2) * 36 + c + 8 * kt];
                uint32_t b1 = Vs[(r + 8 * nt2) * 36 + c + 8 * kt + 4];
                mma_bf16(oacc[nt2], a0, a1, a2, a3, b0, b1);
            }
        }
    }

    // ---- write out: att[(b*C + h*32 + d)*N + i] ----
    const float inv0 = 1.f / l0, inv1 = 1.f / l1;
    const int r = lane >> 2, c = lane & 3;
    const int i0 = q0 + 16 * w + r;
    float* ob = out + ((size_t)b * C_ + (size_t)h * HD) * N_;
    #pragma unroll
    for (int nt2 = 0; nt2 < 4; nt2++) {
        int d = 8 * nt2 + 2 * c;
        ob[(size_t)d       * N_ + i0]     = oacc[nt2][0] * inv0;
        ob[(size_t)(d + 1) * N_ + i0]     = oacc[nt2][1] * inv0;
        ob[(size_t)d       * N_ + i0 + 8] = oacc[nt2][2] * inv1;
        ob[(size_t)(d + 1) * N_ + i0 + 8] = oacc[nt2][3] * inv1;
    }
}

// ---------------------------------------------------------------------------
// Launch
// ---------------------------------------------------------------------------
extern "C" void kernel_launch(void* const* d_in, const int* in_sizes, int n_in,
                              void* d_out, int out_size)
{
    const float* x      = (const float*)d_in[0];
    const float* w_qkv  = (const float*)d_in[1];
    const float* w_out  = (const float*)d_in[2];
    const float* b_out  = (const float*)d_in[3];
    const float* temper = (const float*)d_in[4];
    const float* g1     = (const float*)d_in[5];
    const float* beta1  = (const float*)d_in[6];
    const float* g2     = (const float*)d_in[7];
    const float* beta2  = (const float*)d_in[8];
    const float* w_mlp1 = (const float*)d_in[9];
    const float* b_mlp1 = (const float*)d_in[10];
    const float* w_mlp2 = (const float*)d_in[11];
    const float* b_mlp2 = (const float*)d_in[12];
    float* outp = (float*)d_out;

    float *xn, *qkv, *qkT, *att, *x2, *y, *hb;
    cudaGetSymbolAddress((void**)&xn,  g_xn);
    cudaGetSymbolAddress((void**)&qkv, g_qkv);
    cudaGetSymbolAddress((void**)&qkT, g_qkT);
    cudaGetSymbolAddress((void**)&att, g_att);
    cudaGetSymbolAddress((void**)&x2,  g_x2);
    cudaGetSymbolAddress((void**)&y,   g_y);
    cudaGetSymbolAddress((void**)&hb,  g_h);

    // 1) GroupNorm 1
    groupnorm_k<<<dim3(GROUPS, B_), 256>>>(x, g1, beta1, xn);
    // 2) QKV 1x1 conv
    sgemm_k<false, false, false><<<dim3(N_ / 64, (3 * C_) / 64, B_), 256>>>(
        w_qkv, xn, nullptr, nullptr, qkv, 3 * C_, C_, N_);
    // 2b) transpose q,k to token-major
    transpose_qk<<<dim3(N_ / 32, HEADS, 2 * B_), dim3(32, 8)>>>(qkv, qkT);
    // 3) Attention (mma.sync: tf32 QK^T, bf16 PV)
    flash_mma<<<dim3(N_ / 64, HEADS, B_), 128>>>(qkT, qkv, temper, att);
    // 4) Out-proj + bias + residual(x)
    sgemm_k<true, true, false><<<dim3(N_ / 64, C_ / 64, B_), 256>>>(
        w_out, att, b_out, x, x2, C_, C_, N_);
    // 5) GroupNorm 2
    groupnorm_k<<<dim3(GROUPS, B_), 256>>>(x2, g2, beta2, y);
    // 6) MLP1 + bias + gelu
    sgemm_k<true, false, true><<<dim3(N_ / 64, HID / 64, B_), 256>>>(
        w_mlp1, y, b_mlp1, nullptr, hb, HID, C_, N_);
    // 7) MLP2 + bias + residual(x2) -> output
    sgemm_k<true, true, false><<<dim3(N_ / 64, C_ / 64, B_), 256>>>(
        w_mlp2, hb, b_mlp2, x2, outp, C_, HID, N_);
}